// round 4
// baseline (speedup 1.0000x reference)
#include <cuda_runtime.h>

#define H    16
#define NBOX 128
#define DIN  256
#define DKD  128
#define DG   64

typedef unsigned long long ull;

// Scratch (device globals — no allocations allowed)
__device__ float g_glog[H * NBOX * NBOX];      // log(clip(relu(gate))): 1 MB
__device__ float g_qkv[3 * H * NBOX * DKD];    // k,q,v projections: 3 MB
__device__ float g_partial[H * 4 * DKD];       // per-mtile partial colsums

// ---- packed f32x2 helpers (sm_10x FFMA2) ----------------------------------
__device__ __forceinline__ void fma2(ull& acc, ull a, ull b) {
    asm("fma.rn.f32x2 %0, %1, %2, %0;" : "+l"(acc) : "l"(a), "l"(b));
}
__device__ __forceinline__ ull dup2(float a) {
    ull r; asm("mov.b64 %0, {%1, %1};" : "=l"(r) : "f"(a)); return r;
}
__device__ __forceinline__ float2 unpack2(ull v) {
    float2 r; asm("mov.b64 {%0, %1}, %2;" : "=f"(r.x), "=f"(r.y) : "l"(v)); return r;
}

// ---------------------------------------------------------------------------
// k_front (128 threads/block, 448 blocks):
//   blocks [0,192):   proj tile 32x128: C = f_a(32x256) @ W[h,p](256x128) + b
//     * A staged in smem ONCE (single __syncthreads), pad-258 row-major;
//       main-loop LDS.32 conflict-free broadcast.
//     * B streamed straight from global: 4 near-uniform LDG.128 per d.
//     * thread = rows {tr, tr+16} x cols [16tc, 16tc+16); 16 FFMA2 per d.
//     * NO syncs in the 256-d loop -> scoreboard-pipelined.
//   blocks [192,448): gate: glog[h,m,n] = log(max(pos[m,n,:]·WG[h]+bg[h],1e-6))
// ---------------------------------------------------------------------------
__global__ void __launch_bounds__(128) k_front(
        const float* __restrict__ f_a,
        const float* __restrict__ pos,
        const float* __restrict__ WG, const float* __restrict__ bg,
        const float* __restrict__ WK, const float* __restrict__ bk,
        const float* __restrict__ WQ, const float* __restrict__ bq,
        const float* __restrict__ WV, const float* __restrict__ bv) {
    __shared__ __align__(16) char smem_raw[33024];   // proj 33024 B / gate 20736 B
    int tid = threadIdx.x;

    if (blockIdx.x < 192) {
        // ---------------- proj path ----------------
        float (*AsR)[258] = (float(*)[258])smem_raw;   // 32 rows x (256+2 pad)

        int bid = blockIdx.x;
        int mt = bid & 3;
        int p  = (bid >> 2) % 3;
        int h  = bid / 12;
        const float* W  = (p == 0) ? WK : ((p == 1) ? WQ : WV);
        const float* bb = (p == 0) ? bk : ((p == 1) ? bq : bv);

        int m0 = mt * 32;
        int tr = tid & 15;      // rows tr, tr+16
        int tc = tid >> 4;      // cols 16tc .. 16tc+15

        // Fill A once: coalesced float4 global loads, STS.64 pair stores.
#pragma unroll
        for (int it = 0; it < 16; ++it) {
            int fidx = tid + 128 * it;
            int r = fidx >> 6, c4 = fidx & 63;
            float4 v = *(const float4*)&f_a[(m0 + r) * DIN + 4 * c4];
            AsR[r][4 * c4 + 0] = v.x;
            AsR[r][4 * c4 + 1] = v.y;
            AsR[r][4 * c4 + 2] = v.z;
            AsR[r][4 * c4 + 3] = v.w;
        }
        __syncthreads();

        const ulonglong2* Wg = (const ulonglong2*)(W + (long)h * DIN * DKD);
        ull acc[2][8] = {};

#pragma unroll 4
        for (int d = 0; d < DIN; ++d) {
            ull A0 = dup2(AsR[tr][d]);
            ull A1 = dup2(AsR[tr + 16][d]);
            ulonglong2 b0 = Wg[32 * d + 4 * tc + 0];
            ulonglong2 b1 = Wg[32 * d + 4 * tc + 1];
            ulonglong2 b2 = Wg[32 * d + 4 * tc + 2];
            ulonglong2 b3 = Wg[32 * d + 4 * tc + 3];
            fma2(acc[0][0], A0, b0.x);  fma2(acc[0][1], A0, b0.y);
            fma2(acc[0][2], A0, b1.x);  fma2(acc[0][3], A0, b1.y);
            fma2(acc[0][4], A0, b2.x);  fma2(acc[0][5], A0, b2.y);
            fma2(acc[0][6], A0, b3.x);  fma2(acc[0][7], A0, b3.y);
            fma2(acc[1][0], A1, b0.x);  fma2(acc[1][1], A1, b0.y);
            fma2(acc[1][2], A1, b1.x);  fma2(acc[1][3], A1, b1.y);
            fma2(acc[1][4], A1, b2.x);  fma2(acc[1][5], A1, b2.y);
            fma2(acc[1][6], A1, b3.x);  fma2(acc[1][7], A1, b3.y);
        }

        float* outp = g_qkv + (long)(p * H + h) * NBOX * DKD;
#pragma unroll
        for (int i = 0; i < 2; ++i) {
            int row = m0 + tr + 16 * i;
#pragma unroll
            for (int q = 0; q < 4; ++q) {
                int col = 16 * tc + 4 * q;
                float2 lo = unpack2(acc[i][2 * q + 0]);
                float2 hi = unpack2(acc[i][2 * q + 1]);
                float4 b4 = *(const float4*)&bb[h * DKD + col];
                *(float4*)&outp[row * DKD + col] =
                    make_float4(lo.x + b4.x, lo.y + b4.y, hi.x + b4.z, hi.y + b4.w);
            }
        }
    } else {
        // ---------------- gate path ----------------
        float (*pos_s)[65] = (float(*)[65])smem_raw;             // 64x65 = 16640 B
        float* wg_s = (float*)(smem_raw + 64 * 65 * 4);          // 16x64 =  4096 B

        int p0 = (blockIdx.x - 192) * 64;   // pair base (pair = m*128+n)

#pragma unroll
        for (int it = 0; it < 2; ++it)
            ((float4*)wg_s)[tid + 128 * it] = ((const float4*)WG)[tid + 128 * it];
#pragma unroll
        for (int it = 0; it < 8; ++it) {
            int fidx = tid + 128 * it;
            int pl = fidx >> 4, g4 = fidx & 15;
            float4 v = ((const float4*)pos)[(long)(p0 + pl) * 16 + g4];
            pos_s[pl][4 * g4 + 0] = v.x;
            pos_s[pl][4 * g4 + 1] = v.y;
            pos_s[pl][4 * g4 + 2] = v.z;
            pos_s[pl][4 * g4 + 3] = v.w;
        }
        __syncthreads();

        int row = tid & 63;
        int hg  = tid >> 6;       // 0..1 -> heads {hg, hg+2, ..., hg+14}
        float acc[8] = {};
#pragma unroll
        for (int g = 0; g < DG; ++g) {
            float pv = pos_s[row][g];
#pragma unroll
            for (int j = 0; j < 8; ++j)
                acc[j] = fmaf(pv, wg_s[(hg + 2 * j) * DG + g], acc[j]);
        }
#pragma unroll
        for (int j = 0; j < 8; ++j) {
            int h = hg + 2 * j;
            float x = acc[j] + bg[h];
            g_glog[h * (NBOX * NBOX) + p0 + row] = __logf(fmaxf(x, 1e-6f));
        }
    }
}

// ---------------------------------------------------------------------------
// k_attn: 32x128 score tile (f32x2 FMA), + glog, row softmax, partial colsums.
// grid (4, 16), 256 threads.
// ---------------------------------------------------------------------------
__global__ void k_attn() {
    __shared__ __align__(16) ull As2[32][33];
    __shared__ __align__(16) float Bs[32][132];
    __shared__ float psum[8][128];

    int tid = threadIdx.x;
    int mt = blockIdx.x, h = blockIdx.y;
    int m0 = mt * 32;
    int rg = tid >> 5;
    int cg = tid & 31;

    const float* kmat = g_qkv + (long)(0 * H + h) * NBOX * DKD;
    const float* qmat = g_qkv + (long)(1 * H + h) * NBOX * DKD;

    ull acc[4][2] = {};

    for (int kk = 0; kk < DKD; kk += 32) {
        {
            int r = tid >> 3, c4 = tid & 7;
            float4 v = *(const float4*)&kmat[(m0 + r) * DKD + kk + 4 * c4];
            As2[r][4 * c4 + 0] = dup2(v.x);
            As2[r][4 * c4 + 1] = dup2(v.y);
            As2[r][4 * c4 + 2] = dup2(v.z);
            As2[r][4 * c4 + 3] = dup2(v.w);
        }
#pragma unroll
        for (int it = 0; it < 4; ++it) {
            int fidx = tid + 256 * it;
            int n = fidx >> 3, c4 = fidx & 7;
            float4 v = *(const float4*)&qmat[n * DKD + kk + 4 * c4];
            Bs[4 * c4 + 0][n] = v.x;
            Bs[4 * c4 + 1][n] = v.y;
            Bs[4 * c4 + 2][n] = v.z;
            Bs[4 * c4 + 3][n] = v.w;
        }
        __syncthreads();

#pragma unroll
        for (int d = 0; d < 32; ++d) {
            ulonglong2 b = *(ulonglong2*)&Bs[d][4 * cg];
#pragma unroll
            for (int i = 0; i < 4; ++i) {
                ull a = As2[4 * rg + i][d];
                fma2(acc[i][0], a, b.x);
                fma2(acc[i][1], a, b.y);
            }
        }
        __syncthreads();
    }

    const float scale = 0.08838834764831843f;  // 1/sqrt(128)
    float csum[4] = {0.f, 0.f, 0.f, 0.f};
#pragma unroll
    for (int i = 0; i < 4; ++i) {
        int m = m0 + 4 * rg + i;
        float4 gl = *(const float4*)&g_glog[((long)h * NBOX + m) * NBOX + 4 * cg];
        float2 s0 = unpack2(acc[i][0]);
        float2 s1 = unpack2(acc[i][1]);
        float l[4];
        l[0] = s0.x * scale + gl.x;
        l[1] = s0.y * scale + gl.y;
        l[2] = s1.x * scale + gl.z;
        l[3] = s1.y * scale + gl.w;

        float mx = fmaxf(fmaxf(l[0], l[1]), fmaxf(l[2], l[3]));
#pragma unroll
        for (int off = 16; off; off >>= 1)
            mx = fmaxf(mx, __shfl_xor_sync(0xffffffffu, mx, off));

        float e[4], s = 0.f;
#pragma unroll
        for (int j = 0; j < 4; ++j) { e[j] = __expf(l[j] - mx); s += e[j]; }
#pragma unroll
        for (int off = 16; off; off >>= 1)
            s += __shfl_xor_sync(0xffffffffu, s, off);

        float rinv = 1.0f / s;
#pragma unroll
        for (int j = 0; j < 4; ++j) csum[j] += e[j] * rinv;
    }

#pragma unroll
    for (int j = 0; j < 4; ++j) psum[rg][4 * cg + j] = csum[j];
    __syncthreads();

    if (tid < 128) {
        float s = 0.f;
#pragma unroll
        for (int ww = 0; ww < 8; ++ww) s += psum[ww][tid];
        g_partial[(h * 4 + mt) * DKD + tid] = s;
    }
}

// ---------------------------------------------------------------------------
// k_out: out[i, c, d] = v[h,i,k]*colsum[h,k] + f_a[i,d]   (c = h*128+k)
// colsum computed inline from 4 partials. 16.7M float4 streaming stores.
// ---------------------------------------------------------------------------
__global__ void k_out(const float* __restrict__ f_a, float4* __restrict__ out) {
    int idx = blockIdx.x * 512 + threadIdx.x;   // 0..2^24-1
    int d4 = idx & 63;
    int c  = (idx >> 6) & 2047;
    int i  = idx >> 17;
    int h  = c >> 7;
    int k  = c & 127;

    float cs = g_partial[(h * 4 + 0) * DKD + k]
             + g_partial[(h * 4 + 1) * DKD + k]
             + g_partial[(h * 4 + 2) * DKD + k]
             + g_partial[(h * 4 + 3) * DKD + k];
    float s = g_qkv[((long)(2 * H + h) * NBOX + i) * DKD + k] * cs;
    float4 f = ((const float4*)f_a)[i * 64 + d4];
    __stcs(&out[idx], make_float4(s + f.x, s + f.y, s + f.z, s + f.w));
}

// ---------------------------------------------------------------------------
extern "C" void kernel_launch(void* const* d_in, const int* in_sizes, int n_in,
                              void* d_out, int out_size) {
    const float* f_a = (const float*)d_in[0];
    const float* pos = (const float*)d_in[1];
    const float* WG  = (const float*)d_in[2];
    const float* bg  = (const float*)d_in[3];
    const float* WK  = (const float*)d_in[4];
    const float* bk  = (const float*)d_in[5];
    const float* WQ  = (const float*)d_in[6];
    const float* bq  = (const float*)d_in[7];
    const float* WV  = (const float*)d_in[8];
    const float* bv  = (const float*)d_in[9];

    k_front<<<448, 128>>>(f_a, pos, WG, bg, WK, bk, WQ, bq, WV, bv);
    k_attn<<<dim3(4, 16), 256>>>();
    k_out<<<32768, 512>>>(f_a, (float4*)d_out);
}

// round 5
// speedup vs baseline: 1.1471x; 1.1471x over previous
#include <cuda_runtime.h>

#define H    16
#define NBOX 128
#define DIN  256
#define DKD  128
#define DG   64

typedef unsigned long long ull;

// Scratch (device globals — no allocations allowed)
__device__ float g_glog[H * NBOX * NBOX];      // log(clip(relu(gate))): 1 MB
__device__ float g_qkv[3 * H * NBOX * DKD];    // k,q,v projections: 3 MB
__device__ float g_partial[H * 4 * DKD];       // per-mtile partial colsums

// ---- packed f32x2 helpers (sm_10x FFMA2) ----------------------------------
__device__ __forceinline__ void fma2(ull& acc, ull a, ull b) {
    asm("fma.rn.f32x2 %0, %1, %2, %0;" : "+l"(acc) : "l"(a), "l"(b));
}
__device__ __forceinline__ ull dup2(float a) {
    ull r; asm("mov.b64 %0, {%1, %1};" : "=l"(r) : "f"(a)); return r;
}
__device__ __forceinline__ float2 unpack2(ull v) {
    float2 r; asm("mov.b64 {%0, %1}, %2;" : "=f"(r.x), "=f"(r.y) : "l"(v)); return r;
}

// ---------------------------------------------------------------------------
// k_front (256 threads):
//   blocks [0,96):  proj tile 64x128: C = f_a(64x256) @ W[h,p](256x128) + b
//     Inner loop per d: A read WARP-UNIFORM from transposed smem (4x LDS.128
//     broadcast = 4 wf), B read per-lane coalesced (1x LDS.64 = 2 wf),
//     16 FFMA2 (=32 FMA-issue cyc) -> LDS at 75% of FMA: FMA-pipe-bound.
//     Global loads hidden via register-prefetch (chunk c+1 staged in regs
//     while chunk c computes).
//   blocks [96,352): gate: glog[h,m,n] = log(max(pos[m,n,:]·WG[h]+bg[h],1e-6))
// ---------------------------------------------------------------------------
__global__ void __launch_bounds__(256) k_front(
        const float* __restrict__ f_a,
        const float* __restrict__ pos,
        const float* __restrict__ WG, const float* __restrict__ bg,
        const float* __restrict__ WK, const float* __restrict__ bk,
        const float* __restrict__ WQ, const float* __restrict__ bq,
        const float* __restrict__ WV, const float* __restrict__ bv) {
    __shared__ __align__(16) char smem_raw[25600];
    int tid = threadIdx.x;

    if (blockIdx.x < 96) {
        // ---------------- proj path ----------------
        // AsT[d][row]: A chunk transposed, 32 x 68 pad (stride 272B, 16B-mult)
        // Bs[d][col] : B chunk row-major,  32 x 132 pad (stride 528B)
        float (*AsT)[68] = (float(*)[68])smem_raw;                 // 8704 B
        float (*Bs)[132] = (float(*)[132])(smem_raw + 8704);       // 16896 B

        int bid = blockIdx.x;
        int mt = bid & 1;
        int p  = (bid >> 1) % 3;
        int h  = bid / 6;
        const float* W  = (p == 0) ? WK : ((p == 1) ? WQ : WV);
        const float* bb = (p == 0) ? bk : ((p == 1) ? bq : bv);
        const float* Wh = W + (long)h * DIN * DKD;

        int m0 = mt * 64;
        int w  = tid >> 5, L = tid & 31;
        int r0 = 16 * (w >> 1);        // warp row group: 16 rows
        int col = 64 * (w & 1) + 2 * L; // 2 adjacent cols per thread

        // prefetch registers
        float4 pa[2], pb[4];

        // A-load indices (fixed per thread)
        int a_row = tid >> 3;          // two rows: a_row, a_row via it... rows via fidx
        int a_c4  = tid & 7;

#define LOAD_REGS(KK)                                                          \
        {                                                                      \
            _Pragma("unroll")                                                  \
            for (int it = 0; it < 2; ++it) {                                   \
                int fidx = tid + 256 * it;                                     \
                int r = fidx >> 3, c4 = fidx & 7;                              \
                pa[it] = *(const float4*)&f_a[(m0 + r) * DIN + (KK) + 4 * c4]; \
            }                                                                  \
            _Pragma("unroll")                                                  \
            for (int it = 0; it < 4; ++it) {                                   \
                int fidx = tid + 256 * it;                                     \
                int d = fidx >> 5, c4 = fidx & 31;                             \
                pb[it] = *(const float4*)&Wh[((KK) + d) * DKD + 4 * c4];       \
            }                                                                  \
        }

#define STS_REGS()                                                             \
        {                                                                      \
            _Pragma("unroll")                                                  \
            for (int it = 0; it < 2; ++it) {                                   \
                int fidx = tid + 256 * it;                                     \
                int r = fidx >> 3, c4 = fidx & 7;                              \
                AsT[4 * c4 + 0][r] = pa[it].x;                                 \
                AsT[4 * c4 + 1][r] = pa[it].y;                                 \
                AsT[4 * c4 + 2][r] = pa[it].z;                                 \
                AsT[4 * c4 + 3][r] = pa[it].w;                                 \
            }                                                                  \
            _Pragma("unroll")                                                  \
            for (int it = 0; it < 4; ++it) {                                   \
                int fidx = tid + 256 * it;                                     \
                int d = fidx >> 5, c4 = fidx & 31;                             \
                *(float4*)&Bs[d][4 * c4] = pb[it];                             \
            }                                                                  \
        }

        ull acc[8][2] = {};   // acc[j][i]: rows {r0+2j, r0+2j+1}, col {col+i}

        LOAD_REGS(0);
        STS_REGS();
        __syncthreads();
        LOAD_REGS(32);

        for (int c = 0; c < 8; ++c) {
#pragma unroll 4
            for (int d = 0; d < 32; ++d) {
                ulonglong2 au0 = *(ulonglong2*)&AsT[d][r0 + 0];
                ulonglong2 au1 = *(ulonglong2*)&AsT[d][r0 + 4];
                ulonglong2 au2 = *(ulonglong2*)&AsT[d][r0 + 8];
                ulonglong2 au3 = *(ulonglong2*)&AsT[d][r0 + 12];
                float2 bf = *(float2*)&Bs[d][col];
                ull b0 = dup2(bf.x);
                ull b1 = dup2(bf.y);
                fma2(acc[0][0], au0.x, b0);  fma2(acc[0][1], au0.x, b1);
                fma2(acc[1][0], au0.y, b0);  fma2(acc[1][1], au0.y, b1);
                fma2(acc[2][0], au1.x, b0);  fma2(acc[2][1], au1.x, b1);
                fma2(acc[3][0], au1.y, b0);  fma2(acc[3][1], au1.y, b1);
                fma2(acc[4][0], au2.x, b0);  fma2(acc[4][1], au2.x, b1);
                fma2(acc[5][0], au2.y, b0);  fma2(acc[5][1], au2.y, b1);
                fma2(acc[6][0], au3.x, b0);  fma2(acc[6][1], au3.x, b1);
                fma2(acc[7][0], au3.y, b0);  fma2(acc[7][1], au3.y, b1);
            }
            __syncthreads();
            if (c < 7) {
                STS_REGS();                     // stage chunk c+1
                if (c < 6) LOAD_REGS(32 * (c + 2));
                __syncthreads();
            }
        }
#undef LOAD_REGS
#undef STS_REGS

        float* outp = g_qkv + (long)(p * H + h) * NBOX * DKD;
        float2 ba = *(const float2*)&bb[h * DKD + col];
#pragma unroll
        for (int j = 0; j < 8; ++j) {
            float2 c0v = unpack2(acc[j][0]);   // (row 2j, row 2j+1) @ col
            float2 c1v = unpack2(acc[j][1]);   // (row 2j, row 2j+1) @ col+1
            int row = m0 + r0 + 2 * j;
            *(float2*)&outp[(row + 0) * DKD + col] =
                make_float2(c0v.x + ba.x, c1v.x + ba.y);
            *(float2*)&outp[(row + 1) * DKD + col] =
                make_float2(c0v.y + ba.x, c1v.y + ba.y);
        }
    } else {
        // ---------------- gate path ----------------
        float (*pos_s)[65] = (float(*)[65])smem_raw;             // 64x65 = 16640 B
        float* wg_s = (float*)(smem_raw + 64 * 65 * 4);          // 16x64 =  4096 B

        int p0 = (blockIdx.x - 96) * 64;   // pair base (pair = m*128+n)

        ((float4*)wg_s)[tid] = ((const float4*)WG)[tid];
#pragma unroll
        for (int it = 0; it < 4; ++it) {
            int fidx = tid + 256 * it;
            int pl = fidx >> 4, g4 = fidx & 15;
            float4 v = ((const float4*)pos)[(long)(p0 + pl) * 16 + g4];
            pos_s[pl][4 * g4 + 0] = v.x;
            pos_s[pl][4 * g4 + 1] = v.y;
            pos_s[pl][4 * g4 + 2] = v.z;
            pos_s[pl][4 * g4 + 3] = v.w;
        }
        __syncthreads();

        int row = tid & 63;
        int hg  = tid >> 6;       // heads {hg, hg+4, hg+8, hg+12}
        float acc[4] = {0.f, 0.f, 0.f, 0.f};
#pragma unroll
        for (int g = 0; g < DG; ++g) {
            float pv = pos_s[row][g];
#pragma unroll
            for (int j = 0; j < 4; ++j)
                acc[j] = fmaf(pv, wg_s[(hg + 4 * j) * DG + g], acc[j]);
        }
#pragma unroll
        for (int j = 0; j < 4; ++j) {
            int h = hg + 4 * j;
            float x = acc[j] + bg[h];
            g_glog[h * (NBOX * NBOX) + p0 + row] = __logf(fmaxf(x, 1e-6f));
        }
    }
}

// ---------------------------------------------------------------------------
// k_attn: 32x128 score tile (f32x2 FMA), + glog, row softmax, partial colsums.
// grid (4, 16), 256 threads.
// ---------------------------------------------------------------------------
__global__ void k_attn() {
    __shared__ __align__(16) ull As2[32][33];
    __shared__ __align__(16) float Bs[32][132];
    __shared__ float psum[8][128];

    int tid = threadIdx.x;
    int mt = blockIdx.x, h = blockIdx.y;
    int m0 = mt * 32;
    int rg = tid >> 5;
    int cg = tid & 31;

    const float* kmat = g_qkv + (long)(0 * H + h) * NBOX * DKD;
    const float* qmat = g_qkv + (long)(1 * H + h) * NBOX * DKD;

    ull acc[4][2] = {};

    for (int kk = 0; kk < DKD; kk += 32) {
        {
            int r = tid >> 3, c4 = tid & 7;
            float4 v = *(const float4*)&kmat[(m0 + r) * DKD + kk + 4 * c4];
            As2[r][4 * c4 + 0] = dup2(v.x);
            As2[r][4 * c4 + 1] = dup2(v.y);
            As2[r][4 * c4 + 2] = dup2(v.z);
            As2[r][4 * c4 + 3] = dup2(v.w);
        }
#pragma unroll
        for (int it = 0; it < 4; ++it) {
            int fidx = tid + 256 * it;
            int n = fidx >> 3, c4 = fidx & 7;
            float4 v = *(const float4*)&qmat[n * DKD + kk + 4 * c4];
            Bs[4 * c4 + 0][n] = v.x;
            Bs[4 * c4 + 1][n] = v.y;
            Bs[4 * c4 + 2][n] = v.z;
            Bs[4 * c4 + 3][n] = v.w;
        }
        __syncthreads();

#pragma unroll
        for (int d = 0; d < 32; ++d) {
            ulonglong2 b = *(ulonglong2*)&Bs[d][4 * cg];
#pragma unroll
            for (int i = 0; i < 4; ++i) {
                ull a = As2[4 * rg + i][d];
                fma2(acc[i][0], a, b.x);
                fma2(acc[i][1], a, b.y);
            }
        }
        __syncthreads();
    }

    const float scale = 0.08838834764831843f;  // 1/sqrt(128)
    float csum[4] = {0.f, 0.f, 0.f, 0.f};
#pragma unroll
    for (int i = 0; i < 4; ++i) {
        int m = m0 + 4 * rg + i;
        float4 gl = *(const float4*)&g_glog[((long)h * NBOX + m) * NBOX + 4 * cg];
        float2 s0 = unpack2(acc[i][0]);
        float2 s1 = unpack2(acc[i][1]);
        float l[4];
        l[0] = s0.x * scale + gl.x;
        l[1] = s0.y * scale + gl.y;
        l[2] = s1.x * scale + gl.z;
        l[3] = s1.y * scale + gl.w;

        float mx = fmaxf(fmaxf(l[0], l[1]), fmaxf(l[2], l[3]));
#pragma unroll
        for (int off = 16; off; off >>= 1)
            mx = fmaxf(mx, __shfl_xor_sync(0xffffffffu, mx, off));

        float e[4], s = 0.f;
#pragma unroll
        for (int j = 0; j < 4; ++j) { e[j] = __expf(l[j] - mx); s += e[j]; }
#pragma unroll
        for (int off = 16; off; off >>= 1)
            s += __shfl_xor_sync(0xffffffffu, s, off);

        float rinv = 1.0f / s;
#pragma unroll
        for (int j = 0; j < 4; ++j) csum[j] += e[j] * rinv;
    }

#pragma unroll
    for (int j = 0; j < 4; ++j) psum[rg][4 * cg + j] = csum[j];
    __syncthreads();

    if (tid < 128) {
        float s = 0.f;
#pragma unroll
        for (int ww = 0; ww < 8; ++ww) s += psum[ww][tid];
        g_partial[(h * 4 + mt) * DKD + tid] = s;
    }
}

// ---------------------------------------------------------------------------
// k_out: out[i, c, d] = v[h,i,k]*colsum[h,k] + f_a[i,d]   (c = h*128+k)
// colsum computed inline from 4 partials. 16.7M float4 streaming stores.
// ---------------------------------------------------------------------------
__global__ void k_out(const float* __restrict__ f_a, float4* __restrict__ out) {
    int idx = blockIdx.x * 512 + threadIdx.x;   // 0..2^24-1
    int d4 = idx & 63;
    int c  = (idx >> 6) & 2047;
    int i  = idx >> 17;
    int h  = c >> 7;
    int k  = c & 127;

    float cs = g_partial[(h * 4 + 0) * DKD + k]
             + g_partial[(h * 4 + 1) * DKD + k]
             + g_partial[(h * 4 + 2) * DKD + k]
             + g_partial[(h * 4 + 3) * DKD + k];
    float s = g_qkv[((long)(2 * H + h) * NBOX + i) * DKD + k] * cs;
    float4 f = ((const float4*)f_a)[i * 64 + d4];
    __stcs(&out[idx], make_float4(s + f.x, s + f.y, s + f.z, s + f.w));
}

// ---------------------------------------------------------------------------
extern "C" void kernel_launch(void* const* d_in, const int* in_sizes, int n_in,
                              void* d_out, int out_size) {
    const float* f_a = (const float*)d_in[0];
    const float* pos = (const float*)d_in[1];
    const float* WG  = (const float*)d_in[2];
    const float* bg  = (const float*)d_in[3];
    const float* WK  = (const float*)d_in[4];
    const float* bk  = (const float*)d_in[5];
    const float* WQ  = (const float*)d_in[6];
    const float* bq  = (const float*)d_in[7];
    const float* WV  = (const float*)d_in[8];
    const float* bv  = (const float*)d_in[9];

    k_front<<<352, 256>>>(f_a, pos, WG, bg, WK, bk, WQ, bq, WV, bv);
    k_attn<<<dim3(4, 16), 256>>>();
    k_out<<<32768, 512>>>(f_a, (float4*)d_out);
}